// round 14
// baseline (speedup 1.0000x reference)
#include <cuda_runtime.h>
#include <cuda_bf16.h>
#include <cstdint>
#include <math.h>

#define CCH  192
#define LTT  94
#define NTT  93
#define NNN  187
#define OO   256
#define SIGD 37056
#define EVD  64

__device__ __nv_bfloat16 d_Ahi[2][4][96][CCH];
__device__ __nv_bfloat16 d_Alo[2][4][96][CCH];
__device__ float d_ATf[2][4][96][CCH];
__device__ float d_P[2][4][NTT][OO];
__device__ float d_dummy;

__device__ __forceinline__ void split_bf16(float v, __nv_bfloat16& hi, __nv_bfloat16& lo) {
    hi = __float2bfloat16(v);
    lo = __float2bfloat16(v - __bfloat162float(hi));
}
__device__ __forceinline__ uint32_t smem_u32(const void* p) {
    uint32_t a;
    asm("{ .reg .u64 t; cvta.to.shared.u64 t, %1; cvt.u32.u64 %0, t; }" : "=r"(a) : "l"(p));
    return a;
}
__device__ __forceinline__ void ldsm_x4(uint32_t* r, uint32_t addr) {
    asm volatile("ldmatrix.sync.aligned.m8n8.x4.shared.b16 {%0,%1,%2,%3}, [%4];"
        : "=r"(r[0]), "=r"(r[1]), "=r"(r[2]), "=r"(r[3]) : "r"(addr));
}
__device__ __forceinline__ void ldsm_x2(uint32_t* r, uint32_t addr) {
    asm volatile("ldmatrix.sync.aligned.m8n8.x2.shared.b16 {%0,%1}, [%2];"
        : "=r"(r[0]), "=r"(r[1]) : "r"(addr));
}
__device__ __forceinline__ void mma16816(float* c, const uint32_t* a, const uint32_t* b) {
    asm volatile("mma.sync.aligned.m16n8k16.row.col.f32.bf16.bf16.f32 "
        "{%0,%1,%2,%3}, {%4,%5,%6,%7}, {%8,%9}, {%0,%1,%2,%3};"
        : "+f"(c[0]), "+f"(c[1]), "+f"(c[2]), "+f"(c[3])
        : "r"(a[0]), "r"(a[1]), "r"(a[2]), "r"(a[3]), "r"(b[0]), "r"(b[1]));
}
#define TENSOR_BAR() asm volatile("bar.sync 1, 128;" ::: "memory")

__global__ void k_dummy() { d_dummy = 1.0f; }

// ---------------------------------------------------------------------------
#define AUG_SMEM (12096 * 4 + 128 * 65 * 4)

__global__ __launch_bounds__(256) void k_augment(
    const float* __restrict__ qg, const float* __restrict__ kg,
    const float* __restrict__ Wq1, const float* __restrict__ bq1,
    const float* __restrict__ Wq2, const float* __restrict__ bq2,
    const float* __restrict__ Wk1, const float* __restrict__ bk1,
    const float* __restrict__ Wk2, const float* __restrict__ bk2)
{
    extern __shared__ float dyn[];
    float* W1s = dyn;
    float* W2s = dyn + 12096;
    __shared__ float xs[8][65];
    __shared__ float y1s[64][6];

    int wh = blockIdx.x;
    int w = wh >> 2, head = wh & 3;
    int b = head >> 1, h = head & 1;
    int t0 = blockIdx.y * 6;
    const float* x  = w ? kg  : qg;
    const float* W1 = w ? Wk1 : Wq1;
    const float* B1 = w ? bk1 : bq1;
    const float* W2 = w ? Wk2 : Wq2;
    const float* B2 = w ? bk2 : bq2;
    int tid = threadIdx.x;

    const float4* W1v = (const float4*)W1;
    for (int g = tid; g < 3024; g += 256) ((float4*)W1s)[g] = W1v[g];
    const float4* W2v = (const float4*)W2;
    for (int g = tid; g < 2048; g += 256) {
        float4 vv = W2v[g];
        int c = (g * 4) >> 6, j = (g * 4) & 63;
        float* dst = W2s + c * 65 + j;
        dst[0] = vv.x; dst[1] = vv.y; dst[2] = vv.z; dst[3] = vv.w;
    }
    for (int idx = tid; idx < 8 * 63; idx += 256) {
        int r = idx / 63, e = idx - r * 63;
        int l = t0 + r;
        if (l < 96) xs[r][e] = x[((b * 96 + l) * 2 + h) * 63 + e];
    }
    __syncthreads();

    for (int idx = tid; idx < 64 * 6; idx += 256) {
        int c = idx / 6, tl = idx - c * 6;
        int t = t0 + tl;
        float acc = 0.0f;
        if (t < LTT) {
            const float* wr = W1s + c * 189;
            float a0 = 0, a1 = 0, a2 = 0;
            #pragma unroll 9
            for (int e = 0; e < 63; e++) {
                a0 += wr[e * 3 + 0] * xs[tl][e];
                a1 += wr[e * 3 + 1] * xs[tl + 1][e];
                a2 += wr[e * 3 + 2] * xs[tl + 2][e];
            }
            acc = B1[c] + a0 + a1 + a2;
        }
        y1s[c][tl] = acc;
    }
    __syncthreads();

    for (int idx = tid; idx < 128 * 6; idx += 256) {
        int c = idx / 6, tl = idx - c * 6;
        int t = t0 + tl;
        if (t < LTT) {
            const float* wr = W2s + c * 65;
            float a0 = 0, a1 = 0;
            #pragma unroll
            for (int j = 0; j < 64; j += 2) {
                a0 += wr[j]     * y1s[j][tl];
                a1 += wr[j + 1] * y1s[j + 1][tl];
            }
            float v = fmaxf(B2[c] + a0 + a1, 0.0f);
            __nv_bfloat16 hi, lo;
            split_bf16(v, hi, lo);
            d_Ahi[w][head][t][64 + c] = hi;
            d_Alo[w][head][t][64 + c] = lo;
            d_ATf[w][head][t][64 + c] = v;
        }
    }
    for (int idx = tid; idx < 64 * 6; idx += 256) {
        int tl = idx >> 6, c = idx & 63;
        int t = t0 + tl;
        if (t < LTT) {
            float v = (c == 63) ? (t * (1.0f / 93.0f)) : xs[tl + 2][c];
            __nv_bfloat16 hi, lo;
            split_bf16(v, hi, lo);
            d_Ahi[w][head][t][c] = hi;
            d_Alo[w][head][t][c] = lo;
            d_ATf[w][head][t][c] = v;
        }
    }
    if (blockIdx.y == 15) {
        for (int idx = tid; idx < 2 * CCH; idx += 256) {
            int t = 94 + idx / CCH, c = idx % CCH;
            d_Ahi[w][head][t][c] = __float2bfloat16(0.0f);
            d_Alo[w][head][t][c] = __float2bfloat16(0.0f);
            d_ATf[w][head][t][c] = 0.0f;
        }
    }
}

// ---------------------------------------------------------------------------
// k_proj: hybrid tensor(i<128, 3-pass bf16) + FFMA(i>=128, fp32 exact)
// grid (256,2), 256 thr, 229,376 B smem, 1 CTA/SM
// ---------------------------------------------------------------------------
#define WS2 200
#define ATS 97
#define WFS 193

#define OFF_AHI  0
#define OFF_ALO  38400
#define OFF_WHI  76800
#define OFF_WLO  89600
#define OFF_AT   102400
#define OFF_WF   176896
#define OFF_ACC  226304
#define OFF_E    227840
#define OFF_W1   228224
#define OFF_PREF 228992
#define SM_TOT   229376

__global__ __launch_bounds__(256, 1) void k_proj(
    const float* __restrict__ Wlq, const float* __restrict__ blq,
    const float* __restrict__ Wlk, const float* __restrict__ blk)
{
    extern __shared__ char sm[];
    __nv_bfloat16* Ahi = (__nv_bfloat16*)(sm + OFF_AHI);
    __nv_bfloat16* Alo = (__nv_bfloat16*)(sm + OFF_ALO);
    __nv_bfloat16* Whi = (__nv_bfloat16*)(sm + OFF_WHI);
    __nv_bfloat16* Wlo = (__nv_bfloat16*)(sm + OFF_WLO);
    float* AT    = (float*)(sm + OFF_AT);
    float* WF    = (float*)(sm + OFF_WF);
    float* accS  = (float*)(sm + OFF_ACC);
    float* Esh   = (float*)(sm + OFF_E);
    float* w1sh  = (float*)(sm + OFF_W1);
    float* prefS = (float*)(sm + OFF_PREF);

    int o = blockIdx.x, w = blockIdx.y;
    const float* Wl = w ? Wlk : Wlq;
    const float* bl = w ? blk : blq;
    int tid = threadIdx.x, lane = tid & 31, warp = tid >> 5;

    uint32_t aHiB = smem_u32(Ahi), aLoB = smem_u32(Alo);
    uint32_t wHiB = smem_u32(Whi), wLoB = smem_u32(Wlo);

    for (int g = tid; g < CCH; g += 256) w1sh[g] = Wl[(size_t)o * SIGD + g];
    float blo = bl[o];
    const float* Wbase = Wl + (size_t)o * SIGD + CCH;

    // WF: fp32 W rows i in [128,192), loaded once
    for (int g = tid; g < 64 * CCH; g += 256) {
        int il = g / CCH, k = g - il * CCH;
        WF[il * WFS + k] = Wbase[(128 + il) * CCH + k];
    }

    int wm = warp >> 1, wn = warp & 1;
    uint32_t aRow = 48 * wm + (lane & 15);
    uint32_t aColHalf = (lane >> 4) * 16;
    uint32_t bRowBase = 16 * wn + (lane & 7);
    uint32_t bColHalf = ((lane >> 3) & 1) * 16;
    int r0 = 48 * wm + (lane >> 2);
    int c4 = 2 * (lane & 3);

    int fw = warp - 4;
    int tg = lane >> 3, ig = lane & 7;
    int t_base = 24 * fw + 6 * tg;
    int i_loc = 8 * ig;

    for (int head = 0; head < 4; head++) {
        __syncthreads();
        for (int g = tid; g < 480; g += 256) accS[g] = 0.0f;   // acc + E
        const uint4* srcH = (const uint4*)&d_Ahi[w][head][0][0];
        const uint4* srcL = (const uint4*)&d_Alo[w][head][0][0];
        for (int g = tid; g < 2304; g += 256) {
            int row = g / 24, c8 = g - row * 24;
            *(uint4*)&Ahi[row * WS2 + c8 * 8] = srcH[g];
            *(uint4*)&Alo[row * WS2 + c8 * 8] = srcL[g];
        }
        const float4* srcT = (const float4*)&d_ATf[w][head][0][0];
        for (int g = tid; g < 4608; g += 256) {
            float4 vv = srcT[g];
            int t = g / 48, k4 = (g - t * 48) * 4;
            AT[(k4 + 0) * ATS + t] = vv.x;
            AT[(k4 + 1) * ATS + t] = vv.y;
            AT[(k4 + 2) * ATS + t] = vv.z;
            AT[(k4 + 3) * ATS + t] = vv.w;
        }
        __syncthreads();

        if (warp < 4) {
            // ===== TENSOR: i in [0,128) =====
            float dpa[3][2], dpd[3][2], dpb[3][2], dpg[3][2];
            #pragma unroll
            for (int mt = 0; mt < 3; mt++)
                #pragma unroll
                for (int hr = 0; hr < 2; hr++) {
                    dpa[mt][hr] = 0; dpd[mt][hr] = 0;
                    dpb[mt][hr] = 0; dpg[mt][hr] = 0;
                }

            for (int chunk = 0; chunk < 4; chunk++) {
                const float4* Wc = (const float4*)(Wbase + (size_t)chunk * 32 * CCH);
                #pragma unroll 4
                for (int it = 0; it < 12; it++) {
                    int g = tid + 128 * it;
                    float4 vv = Wc[g];
                    int e0 = g * 4;
                    int i = e0 / CCH, j = e0 - i * CCH;
                    __nv_bfloat16 h0, l0, h1, l1, h2, l2, h3, l3;
                    split_bf16(vv.x, h0, l0); split_bf16(vv.y, h1, l1);
                    split_bf16(vv.z, h2, l2); split_bf16(vv.w, h3, l3);
                    __nv_bfloat162 hp0, hp1, lp0, lp1;
                    hp0.x = h0; hp0.y = h1; hp1.x = h2; hp1.y = h3;
                    lp0.x = l0; lp0.y = l1; lp1.x = l2; lp1.y = l3;
                    uint2 hu, lu;
                    hu.x = *(uint32_t*)&hp0; hu.y = *(uint32_t*)&hp1;
                    lu.x = *(uint32_t*)&lp0; lu.y = *(uint32_t*)&lp1;
                    *(uint2*)&Whi[i * WS2 + j] = hu;
                    *(uint2*)&Wlo[i * WS2 + j] = lu;
                }
                TENSOR_BAR();

                float acc[3][2][4];
                #pragma unroll
                for (int mt = 0; mt < 3; mt++)
                    #pragma unroll
                    for (int nt = 0; nt < 2; nt++)
                        #pragma unroll
                        for (int e = 0; e < 4; e++) acc[mt][nt][e] = 0.0f;

                #pragma unroll
                for (int k = 0; k < 12; k++) {
                    uint32_t kb = k * 32;
                    uint32_t ah[3][4], al[3][4], bh[2][2], blr[2][2];
                    #pragma unroll
                    for (int mt = 0; mt < 3; mt++) {
                        uint32_t off = (aRow + 16u * mt) * 400u + kb + aColHalf;
                        ldsm_x4(ah[mt], aHiB + off);
                        ldsm_x4(al[mt], aLoB + off);
                    }
                    #pragma unroll
                    for (int nt = 0; nt < 2; nt++) {
                        uint32_t off = (bRowBase + 8u * nt) * 400u + kb + bColHalf;
                        ldsm_x2(bh[nt],  wHiB + off);
                        ldsm_x2(blr[nt], wLoB + off);
                    }
                    #pragma unroll
                    for (int mt = 0; mt < 3; mt++)
                        #pragma unroll
                        for (int nt = 0; nt < 2; nt++) {
                            mma16816(acc[mt][nt], ah[mt], bh[nt]);
                            mma16816(acc[mt][nt], ah[mt], blr[nt]);
                            mma16816(acc[mt][nt], al[mt], bh[nt]);
                        }
                }

                #pragma unroll
                for (int mt = 0; mt < 3; mt++) {
                    #pragma unroll
                    for (int hr = 0; hr < 2; hr++) {
                        int t = r0 + 16 * mt + 8 * hr;
                        int tm1 = (t >= 1) ? t - 1 : 0;
                        int tp1 = (t < 95) ? t + 1 : 95;
                        #pragma unroll
                        for (int nt = 0; nt < 2; nt++) {
                            int i0 = chunk * 32 + 16 * wn + 8 * nt + c4;
                            float z0 = acc[mt][nt][2 * hr + 0];
                            float z1 = acc[mt][nt][2 * hr + 1];
                            dpa[mt][hr] += z0 * AT[i0 * ATS + t]   + z1 * AT[(i0 + 1) * ATS + t];
                            dpd[mt][hr] += z0 * AT[i0 * ATS]       + z1 * AT[(i0 + 1) * ATS];
                            dpb[mt][hr] += z0 * AT[i0 * ATS + tm1] + z1 * AT[(i0 + 1) * ATS + tm1];
                            dpg[mt][hr] += z0 * AT[i0 * ATS + tp1] + z1 * AT[(i0 + 1) * ATS + tp1];
                        }
                    }
                }
                TENSOR_BAR();
            }

            #pragma unroll
            for (int mt = 0; mt < 3; mt++) {
                #pragma unroll
                for (int hr = 0; hr < 2; hr++) {
                    int t = r0 + 16 * mt + 8 * hr;
                    float pa = dpa[mt][hr], pd = dpd[mt][hr];
                    float pb = dpb[mt][hr], pg = dpg[mt][hr];
                    #pragma unroll
                    for (int off = 1; off <= 2; off <<= 1) {
                        pa += __shfl_xor_sync(0xffffffffu, pa, off);
                        pd += __shfl_xor_sync(0xffffffffu, pd, off);
                        pb += __shfl_xor_sync(0xffffffffu, pb, off);
                        pg += __shfl_xor_sync(0xffffffffu, pg, off);
                    }
                    if ((lane & 3) == 0 && t < LTT) {
                        atomicAdd(&accS[0 * 96 + t], pa);
                        atomicAdd(&accS[1 * 96 + t], pd);
                        if (t >= 1)  atomicAdd(&accS[2 * 96 + t - 1], pb);
                        if (t <= 92) atomicAdd(&accS[3 * 96 + t], pg);
                    }
                }
            }
        } else {
            // ===== FFMA: i in [128,192) fp32 exact =====
            float z[6][8];
            #pragma unroll
            for (int j = 0; j < 6; j++)
                #pragma unroll
                for (int m = 0; m < 8; m++) z[j][m] = 0.0f;

            for (int k = 0; k < CCH; k++) {
                float a[6];
                #pragma unroll
                for (int j = 0; j < 6; j++) a[j] = AT[k * ATS + t_base + j];
                float wv[8];
                #pragma unroll
                for (int m = 0; m < 8; m++) wv[m] = WF[(i_loc + m) * WFS + k];
                #pragma unroll
                for (int j = 0; j < 6; j++)
                    #pragma unroll
                    for (int m = 0; m < 8; m++) z[j][m] += a[j] * wv[m];
            }

            #pragma unroll
            for (int j = 0; j < 6; j++) {
                int t = t_base + j;
                int tm1 = (t >= 1) ? t - 1 : 0;
                int tp1 = (t < 95) ? t + 1 : 95;
                float pa = 0, pd = 0, pb = 0, pg = 0;
                #pragma unroll
                for (int m = 0; m < 8; m++) {
                    int i2 = 128 + i_loc + m;
                    float zz = z[j][m];
                    pa += zz * AT[i2 * ATS + t];
                    pd += zz * AT[i2 * ATS];
                    pb += zz * AT[i2 * ATS + tm1];
                    pg += zz * AT[i2 * ATS + tp1];
                }
                #pragma unroll
                for (int off = 1; off <= 4; off <<= 1) {
                    pa += __shfl_xor_sync(0xffffffffu, pa, off);
                    pd += __shfl_xor_sync(0xffffffffu, pd, off);
                    pb += __shfl_xor_sync(0xffffffffu, pb, off);
                    pg += __shfl_xor_sync(0xffffffffu, pg, off);
                }
                if (ig == 0 && t < LTT) {
                    atomicAdd(&accS[0 * 96 + t], pa);
                    atomicAdd(&accS[1 * 96 + t], pd);
                    if (t >= 1)  atomicAdd(&accS[2 * 96 + t - 1], pb);
                    if (t <= 92) atomicAdd(&accS[3 * 96 + t], pg);
                }
            }

            // e_t (threads 128..221 -> t = tid-128)
            int t = tid - 128;
            if (t < LTT) {
                float pe = 0.0f;
                for (int k = 0; k < CCH; k++) pe += w1sh[k] * AT[k * ATS + t];
                Esh[t] = pe;
            }
        }
        __syncthreads();

        if (warp == 0) {
            float carry = 0.0f;
            for (int ch = 0; ch < 3; ch++) {
                int idx = ch * 32 + lane;
                float vv = (idx < NTT) ? (accS[2 * 96 + idx] - accS[3 * 96 + idx]) : 0.0f;
                #pragma unroll
                for (int off = 1; off < 32; off <<= 1) {
                    float n = __shfl_up_sync(0xffffffffu, vv, off);
                    if (lane >= off) vv += n;
                }
                vv += carry;
                if (idx < NTT) prefS[idx] = vv;
                carry = __shfl_sync(0xffffffffu, vv, 31);
            }
        }
        __syncthreads();
        if (tid < NTT) {
            int t = tid;
            float Pv = blo + Esh[t + 1] - Esh[0]
                     + 0.5f * (accS[0 * 96 + t + 1] + accS[0 * 96 + 0])
                     - accS[1 * 96 + t + 1]
                     + 0.5f * prefS[t];
            d_P[w][head][t][o] = Pv;
        }
    }
}

// ---------------------------------------------------------------------------
#define TS 260

__global__ __launch_bounds__(256) void k_attn(
    const float* __restrict__ v, float* __restrict__ out)
{
    extern __shared__ float sm3[];
    float* Tq = sm3;
    float* Tk = Tq + NTT * TS;
    float* vg = Tk + NTT * TS;
    float* Gr = vg + NTT * EVD;

    int bh = blockIdx.x, zh = blockIdx.y;
    int tid = threadIdx.x, lane = tid & 31, warp = tid >> 5;

    for (int g = tid; g < NTT * OO; g += 256) {
        int t = g >> 8, o = g & 255;
        Tq[t * TS + o] = d_P[0][bh][t][o];
        Tk[t * TS + o] = d_P[1][bh][t][o];
    }
    for (int g = tid; g < NTT * EVD; g += 256) {
        int t = g >> 6, e = g & 63;
        float s = v[((size_t)bh * NNN + 2 * t) * EVD + e]
                + v[((size_t)bh * NNN + 2 * t + 1) * EVD + e];
        if (t == 92) s += v[((size_t)bh * NNN + 186) * EVD + e];
        vg[g] = s;
    }
    __syncthreads();

    int x0 = zh * 24;
    for (int xx = 0; xx < 3; xx++) {
        int x = x0 + warp + 8 * xx;
        if (x < NTT) {
            int ty0 = lane, ty1 = lane + 32, ty2 = lane + 64;
            int ty2c = (ty2 < NTT) ? ty2 : 0;
            const float4* tq = (const float4*)(Tq + x * TS);
            const float4* k0 = (const float4*)(Tk + ty0 * TS);
            const float4* k1 = (const float4*)(Tk + ty1 * TS);
            const float4* k2 = (const float4*)(Tk + ty2c * TS);
            float a0 = 0, a1 = 0, a2 = 0;
            #pragma unroll 8
            for (int o4 = 0; o4 < OO / 4; o4++) {
                float4 qv = tq[o4];
                float4 b0 = k0[o4];
                a0 += qv.x * b0.x + qv.y * b0.y + qv.z * b0.z + qv.w * b0.w;
                float4 b1 = k1[o4];
                a1 += qv.x * b1.x + qv.y * b1.y + qv.z * b1.z + qv.w * b1.w;
                float4 b2 = k2[o4];
                a2 += qv.x * b2.x + qv.y * b2.y + qv.z * b2.z + qv.w * b2.w;
            }
            __syncwarp();
            Gr[warp * 96 + ty0] = tanhf(a0);
            Gr[warp * 96 + ty1] = tanhf(a1);
            if (ty2 < NTT) Gr[warp * 96 + ty2] = tanhf(a2);
            __syncwarp();
            float o0 = 0, o1 = 0;
            for (int ty = 0; ty < NTT; ty++) {
                float g = Gr[warp * 96 + ty];
                o0 += g * vg[ty * EVD + lane];
                o1 += g * vg[ty * EVD + lane + 32];
            }
            size_t base = ((size_t)bh * NNN + 2 * x) * EVD;
            out[base + lane]            = o0;
            out[base + lane + 32]       = o1;
            out[base + EVD + lane]      = o0;
            out[base + EVD + lane + 32] = o1;
            if (x == 92) {
                size_t bl2 = ((size_t)bh * NNN + 186) * EVD;
                out[bl2 + lane]      = o0;
                out[bl2 + lane + 32] = o1;
            }
        }
    }
}

// ---------------------------------------------------------------------------
extern "C" void kernel_launch(void* const* d_in, const int* in_sizes, int n_in,
                              void* d_out, int out_size)
{
    const float* q   = (const float*)d_in[0];
    const float* k   = (const float*)d_in[1];
    const float* v   = (const float*)d_in[2];
    const float* Wq1 = (const float*)d_in[3];
    const float* bq1 = (const float*)d_in[4];
    const float* Wq2 = (const float*)d_in[5];
    const float* bq2 = (const float*)d_in[6];
    const float* Wk1 = (const float*)d_in[7];
    const float* bk1 = (const float*)d_in[8];
    const float* Wk2 = (const float*)d_in[9];
    const float* bk2 = (const float*)d_in[10];
    const float* Wlq = (const float*)d_in[11];
    const float* blq = (const float*)d_in[12];
    const float* Wlk = (const float*)d_in[13];
    const float* blk = (const float*)d_in[14];
    float* out = (float*)d_out;

    const int SM3 = (2 * NTT * TS + NTT * EVD + 8 * 96) * 4;
    static int attr_done = 0;
    if (!attr_done) {
        cudaFuncSetAttribute(k_augment, cudaFuncAttributeMaxDynamicSharedMemorySize, AUG_SMEM);
        cudaFuncSetAttribute(k_proj, cudaFuncAttributeMaxDynamicSharedMemorySize, SM_TOT);
        cudaFuncSetAttribute(k_attn, cudaFuncAttributeMaxDynamicSharedMemorySize, SM3);
        attr_done = 1;
    }

    k_dummy<<<1, 1>>>();
    k_augment<<<dim3(8, 16), 256, AUG_SMEM>>>(q, k, Wq1, bq1, Wq2, bq2, Wk1, bk1, Wk2, bk2);
    k_proj<<<dim3(256, 2), 256, SM_TOT>>>(Wlq, blq, Wlk, blk);
    k_attn<<<dim3(4, 4), 256, SM3>>>(v, out);
}

// round 16
// speedup vs baseline: 1.5390x; 1.5390x over previous
#include <cuda_runtime.h>
#include <cuda_bf16.h>
#include <cstdint>
#include <math.h>

#define CCH  192
#define LTT  94
#define NTT  93
#define NNN  187
#define OO   256
#define SIGD 37056
#define EVD  64

__device__ __nv_bfloat16 d_Ahi[2][4][96][CCH];
__device__ __nv_bfloat16 d_Alo[2][4][96][CCH];
__device__ float d_P[2][4][NTT][OO];

__device__ __forceinline__ void split_bf16(float v, __nv_bfloat16& hi, __nv_bfloat16& lo) {
    hi = __float2bfloat16(v);
    lo = __float2bfloat16(v - __bfloat162float(hi));
}
__device__ __forceinline__ uint32_t smem_u32(const void* p) {
    uint32_t a;
    asm("{ .reg .u64 t; cvta.to.shared.u64 t, %1; cvt.u32.u64 %0, t; }" : "=r"(a) : "l"(p));
    return a;
}
__device__ __forceinline__ void ldsm_x4(uint32_t* r, uint32_t addr) {
    asm volatile("ldmatrix.sync.aligned.m8n8.x4.shared.b16 {%0,%1,%2,%3}, [%4];"
        : "=r"(r[0]), "=r"(r[1]), "=r"(r[2]), "=r"(r[3]) : "r"(addr));
}
__device__ __forceinline__ void ldsm_x2(uint32_t* r, uint32_t addr) {
    asm volatile("ldmatrix.sync.aligned.m8n8.x2.shared.b16 {%0,%1}, [%2];"
        : "=r"(r[0]), "=r"(r[1]) : "r"(addr));
}
__device__ __forceinline__ void mma16816(float* c, const uint32_t* a, const uint32_t* b) {
    asm volatile("mma.sync.aligned.m16n8k16.row.col.f32.bf16.bf16.f32 "
        "{%0,%1,%2,%3}, {%4,%5,%6,%7}, {%8,%9}, {%0,%1,%2,%3};"
        : "+f"(c[0]), "+f"(c[1]), "+f"(c[2]), "+f"(c[3])
        : "r"(a[0]), "r"(a[1]), "r"(a[2]), "r"(a[3]), "r"(b[0]), "r"(b[1]));
}
__device__ __forceinline__ float2 bf2pair(const __nv_bfloat16* hiP, const __nv_bfloat16* loP) {
    __nv_bfloat162 h = *(const __nv_bfloat162*)hiP;
    __nv_bfloat162 l = *(const __nv_bfloat162*)loP;
    float2 f;
    f.x = __bfloat162float(h.x) + __bfloat162float(l.x);
    f.y = __bfloat162float(h.y) + __bfloat162float(l.y);
    return f;
}

// ---------------------------------------------------------------------------
// Kernel 1: augmentation -> d_Ahi/d_Alo   grid (8, 16), 256 thr
// ---------------------------------------------------------------------------
#define AUG_SMEM (12096 * 4 + 128 * 65 * 4)

__global__ __launch_bounds__(256) void k_augment(
    const float* __restrict__ qg, const float* __restrict__ kg,
    const float* __restrict__ Wq1, const float* __restrict__ bq1,
    const float* __restrict__ Wq2, const float* __restrict__ bq2,
    const float* __restrict__ Wk1, const float* __restrict__ bk1,
    const float* __restrict__ Wk2, const float* __restrict__ bk2)
{
    extern __shared__ float dyn[];
    float* W1s = dyn;
    float* W2s = dyn + 12096;
    __shared__ float xs[8][65];
    __shared__ float y1s[64][6];

    int wh = blockIdx.x;
    int w = wh >> 2, head = wh & 3;
    int b = head >> 1, h = head & 1;
    int t0 = blockIdx.y * 6;
    const float* x  = w ? kg  : qg;
    const float* W1 = w ? Wk1 : Wq1;
    const float* B1 = w ? bk1 : bq1;
    const float* W2 = w ? Wk2 : Wq2;
    const float* B2 = w ? bk2 : bq2;
    int tid = threadIdx.x;

    const float4* W1v = (const float4*)W1;
    for (int g = tid; g < 3024; g += 256) ((float4*)W1s)[g] = W1v[g];
    const float4* W2v = (const float4*)W2;
    for (int g = tid; g < 2048; g += 256) {
        float4 vv = W2v[g];
        int c = (g * 4) >> 6, j = (g * 4) & 63;
        float* dst = W2s + c * 65 + j;
        dst[0] = vv.x; dst[1] = vv.y; dst[2] = vv.z; dst[3] = vv.w;
    }
    for (int idx = tid; idx < 8 * 63; idx += 256) {
        int r = idx / 63, e = idx - r * 63;
        int l = t0 + r;
        if (l < 96) xs[r][e] = x[((b * 96 + l) * 2 + h) * 63 + e];
    }
    __syncthreads();

    for (int idx = tid; idx < 64 * 6; idx += 256) {
        int c = idx / 6, tl = idx - c * 6;
        int t = t0 + tl;
        float acc = 0.0f;
        if (t < LTT) {
            const float* wr = W1s + c * 189;
            float a0 = 0, a1 = 0, a2 = 0;
            #pragma unroll 9
            for (int e = 0; e < 63; e++) {
                a0 += wr[e * 3 + 0] * xs[tl][e];
                a1 += wr[e * 3 + 1] * xs[tl + 1][e];
                a2 += wr[e * 3 + 2] * xs[tl + 2][e];
            }
            acc = B1[c] + a0 + a1 + a2;
        }
        y1s[c][tl] = acc;
    }
    __syncthreads();

    for (int idx = tid; idx < 128 * 6; idx += 256) {
        int c = idx / 6, tl = idx - c * 6;
        int t = t0 + tl;
        if (t < LTT) {
            const float* wr = W2s + c * 65;
            float a0 = 0, a1 = 0;
            #pragma unroll
            for (int j = 0; j < 64; j += 2) {
                a0 += wr[j]     * y1s[j][tl];
                a1 += wr[j + 1] * y1s[j + 1][tl];
            }
            float v = fmaxf(B2[c] + a0 + a1, 0.0f);
            __nv_bfloat16 hi, lo;
            split_bf16(v, hi, lo);
            d_Ahi[w][head][t][64 + c] = hi;
            d_Alo[w][head][t][64 + c] = lo;
        }
    }
    for (int idx = tid; idx < 64 * 6; idx += 256) {
        int tl = idx >> 6, c = idx & 63;
        int t = t0 + tl;
        if (t < LTT) {
            float v = (c == 63) ? (t * (1.0f / 93.0f)) : xs[tl + 2][c];
            __nv_bfloat16 hi, lo;
            split_bf16(v, hi, lo);
            d_Ahi[w][head][t][c] = hi;
            d_Alo[w][head][t][c] = lo;
        }
    }
    if (blockIdx.y == 15) {
        for (int idx = tid; idx < 2 * CCH; idx += 256) {
            int t = 94 + idx / CCH, c = idx % CCH;
            d_Ahi[w][head][t][c] = __float2bfloat16(0.0f);
            d_Alo[w][head][t][c] = __float2bfloat16(0.0f);
        }
    }
}

// ---------------------------------------------------------------------------
// Kernel 2: chunked-W raw-mma bf16 3-pass, register dots, 2 CTAs/SM  (R9)
// grid (256, 2), 256 threads, 111,232 B dynamic smem
// ---------------------------------------------------------------------------
#define WS2 200

#define OFF_AHI  0
#define OFF_ALO  38400
#define OFF_WHI  76800
#define OFF_WLO  89600
#define OFF_ACC  102400
#define OFF_E    108544
#define OFF_W1   110080
#define OFF_PREF 110848
#define SM_TOT   111232

__global__ __launch_bounds__(256, 2) void k_proj(
    const float* __restrict__ Wlq, const float* __restrict__ blq,
    const float* __restrict__ Wlk, const float* __restrict__ blk)
{
    extern __shared__ char sm[];
    __nv_bfloat16* Ahi = (__nv_bfloat16*)(sm + OFF_AHI);
    __nv_bfloat16* Alo = (__nv_bfloat16*)(sm + OFF_ALO);
    __nv_bfloat16* Whi = (__nv_bfloat16*)(sm + OFF_WHI);
    __nv_bfloat16* Wlo = (__nv_bfloat16*)(sm + OFF_WLO);
    float* accS  = (float*)(sm + OFF_ACC);
    float* Esh   = (float*)(sm + OFF_E);
    float* w1sh  = (float*)(sm + OFF_W1);
    float* prefS = (float*)(sm + OFF_PREF);

    int o = blockIdx.x, w = blockIdx.y;
    const float* Wl = w ? Wlk : Wlq;
    const float* bl = w ? blk : blq;
    int tid = threadIdx.x, lane = tid & 31, warp = tid >> 5;
    int wm = warp >> 2, wn = warp & 3;

    uint32_t aHiB = smem_u32(Ahi), aLoB = smem_u32(Alo);
    uint32_t wHiB = smem_u32(Whi), wLoB = smem_u32(Wlo);

    for (int g = tid; g < 4 * 4 * 96; g += 256) accS[g] = 0.0f;
    for (int g = tid; g < CCH; g += 256) w1sh[g] = Wl[(size_t)o * SIGD + g];
    float blo = bl[o];

    const float* Wbase = Wl + (size_t)o * SIGD + CCH;

    uint32_t aRow = 48 * wm + (lane & 15);
    uint32_t aColHalf = (lane >> 4) * 16;
    uint32_t bRow = 8 * wn + (lane & 7);
    uint32_t bColHalf = ((lane >> 3) & 1) * 16;
    int r0 = 48 * wm + (lane >> 2);
    int iw0 = 4 * wn + (lane & 3);

    for (int head = 0; head < 4; head++) {
        __syncthreads();

        const uint4* srcH = (const uint4*)&d_Ahi[w][head][0][0];
        const uint4* srcL = (const uint4*)&d_Alo[w][head][0][0];
        for (int g = tid; g < 2304; g += 256) {
            int row = g / 24, c8 = g - row * 24;
            *(uint4*)&Ahi[row * WS2 + c8 * 8] = srcH[g];
            *(uint4*)&Alo[row * WS2 + c8 * 8] = srcL[g];
        }
        __syncthreads();

        float dpa[3][2], dpd[3][2], dpb[3][2], dpg[3][2];
        #pragma unroll
        for (int mt = 0; mt < 3; mt++)
            #pragma unroll
            for (int hr = 0; hr < 2; hr++) {
                dpa[mt][hr] = 0; dpd[mt][hr] = 0; dpb[mt][hr] = 0; dpg[mt][hr] = 0;
            }

        for (int chunk = 0; chunk < 6; chunk++) {
            const float4* Wc = (const float4*)(Wbase + (size_t)chunk * 32 * CCH);
            for (int g = tid; g < 1536; g += 256) {
                float4 vv = Wc[g];
                int e0 = g * 4;
                int i = e0 / CCH, j = e0 - i * CCH;
                __nv_bfloat16 h0, l0, h1, l1, h2, l2, h3, l3;
                split_bf16(vv.x, h0, l0); split_bf16(vv.y, h1, l1);
                split_bf16(vv.z, h2, l2); split_bf16(vv.w, h3, l3);
                __nv_bfloat162 hp0, hp1, lp0, lp1;
                hp0.x = h0; hp0.y = h1; hp1.x = h2; hp1.y = h3;
                lp0.x = l0; lp0.y = l1; lp1.x = l2; lp1.y = l3;
                uint2 hu, lu;
                hu.x = *(uint32_t*)&hp0; hu.y = *(uint32_t*)&hp1;
                lu.x = *(uint32_t*)&lp0; lu.y = *(uint32_t*)&lp1;
                *(uint2*)&Whi[i * WS2 + j] = hu;
                *(uint2*)&Wlo[i * WS2 + j] = lu;
            }
            __syncthreads();

            float acc[3][4];
            #pragma unroll
            for (int mt = 0; mt < 3; mt++)
                #pragma unroll
                for (int e = 0; e < 4; e++) acc[mt][e] = 0.0f;

            #pragma unroll
            for (int k = 0; k < 12; k++) {
                uint32_t kb = k * 32;
                uint32_t ah[3][4], al[3][4], bh[2], blr[2];
                #pragma unroll
                for (int mt = 0; mt < 3; mt++) {
                    uint32_t off = (aRow + 16u * mt) * 400u + kb + aColHalf;
                    ldsm_x4(ah[mt], aHiB + off);
                    ldsm_x4(al[mt], aLoB + off);
                }
                {
                    uint32_t off = bRow * 400u + kb + bColHalf;
                    ldsm_x2(bh,  wHiB + off);
                    ldsm_x2(blr, wLoB + off);
                }
                #pragma unroll
                for (int mt = 0; mt < 3; mt++) {
                    mma16816(acc[mt], ah[mt], bh);
                    mma16816(acc[mt], ah[mt], blr);
                    mma16816(acc[mt], al[mt], bh);
                }
            }

            int iw = chunk * 16 + iw0;
            #pragma unroll
            for (int mt = 0; mt < 3; mt++) {
                #pragma unroll
                for (int hr = 0; hr < 2; hr++) {
                    int t = r0 + 16 * mt + 8 * hr;
                    int tm1 = (t >= 1) ? t - 1 : 0;
                    int tp1 = (t < 95) ? t + 1 : 95;
                    float z0 = acc[mt][2 * hr + 0];
                    float z1 = acc[mt][2 * hr + 1];
                    float2 at = bf2pair(&Ahi[t   * WS2 + 2 * iw], &Alo[t   * WS2 + 2 * iw]);
                    float2 a0 = bf2pair(&Ahi[2 * iw],             &Alo[2 * iw]);
                    float2 am = bf2pair(&Ahi[tm1 * WS2 + 2 * iw], &Alo[tm1 * WS2 + 2 * iw]);
                    float2 ap = bf2pair(&Ahi[tp1 * WS2 + 2 * iw], &Alo[tp1 * WS2 + 2 * iw]);
                    dpa[mt][hr] += z0 * at.x + z1 * at.y;
                    dpd[mt][hr] += z0 * a0.x + z1 * a0.y;
                    dpb[mt][hr] += z0 * am.x + z1 * am.y;
                    dpg[mt][hr] += z0 * ap.x + z1 * ap.y;
                }
            }
            __syncthreads();
        }

        float* accH = accS + head * 384;
        #pragma unroll
        for (int mt = 0; mt < 3; mt++) {
            #pragma unroll
            for (int hr = 0; hr < 2; hr++) {
                int t = r0 + 16 * mt + 8 * hr;
                float pa = dpa[mt][hr], pd = dpd[mt][hr];
                float pb = dpb[mt][hr], pg = dpg[mt][hr];
                #pragma unroll
                for (int off = 1; off <= 2; off <<= 1) {
                    pa += __shfl_xor_sync(0xffffffffu, pa, off);
                    pd += __shfl_xor_sync(0xffffffffu, pd, off);
                    pb += __shfl_xor_sync(0xffffffffu, pb, off);
                    pg += __shfl_xor_sync(0xffffffffu, pg, off);
                }
                if ((lane & 3) == 0 && t < LTT) {
                    atomicAdd(&accH[0 * 96 + t], pa);
                    atomicAdd(&accH[1 * 96 + t], pd);
                    if (t >= 1)  atomicAdd(&accH[2 * 96 + t - 1], pb);
                    if (t <= 92) atomicAdd(&accH[3 * 96 + t], pg);
                }
            }
        }

        if (tid < 192) {
            int t = tid >> 1, seg = tid & 1;
            float pe = 0.0f;
            #pragma unroll 8
            for (int wd = 0; wd < 48; wd++) {
                int c = seg * 96 + 2 * wd;
                float2 av = bf2pair(&Ahi[t * WS2 + c], &Alo[t * WS2 + c]);
                float2 w1v = *(float2*)&w1sh[c];
                pe += w1v.x * av.x + w1v.y * av.y;
            }
            pe += __shfl_xor_sync(0xffffffffu, pe, 1);
            if (seg == 0 && t < LTT) Esh[head * 96 + t] = pe;
        }
    }
    __syncthreads();

    for (int head = 0; head < 4; head++) {
        float* accH = accS + head * 384;
        float* eH = Esh + head * 96;
        if (warp == 0) {
            float carry = 0.0f;
            for (int ch = 0; ch < 3; ch++) {
                int idx = ch * 32 + lane;
                float vv = (idx < NTT) ? (accH[2 * 96 + idx] - accH[3 * 96 + idx]) : 0.0f;
                #pragma unroll
                for (int off = 1; off < 32; off <<= 1) {
                    float n = __shfl_up_sync(0xffffffffu, vv, off);
                    if (lane >= off) vv += n;
                }
                vv += carry;
                if (idx < NTT) prefS[idx] = vv;
                carry = __shfl_sync(0xffffffffu, vv, 31);
            }
        }
        __syncthreads();
        if (tid < NTT) {
            int t = tid;
            float Pv = blo + eH[t + 1] - eH[0]
                     + 0.5f * (accH[0 * 96 + t + 1] + accH[0 * 96 + 0])
                     - accH[1 * 96 + t + 1]
                     + 0.5f * prefS[t];
            d_P[w][head][t][o] = Pv;
        }
        __syncthreads();
    }
}

// ---------------------------------------------------------------------------
// Kernel 3: attn rows — grid (4 bh, 24 xblk), 4 rows/CTA, 256 thr
// ---------------------------------------------------------------------------
#define TS 260

__global__ __launch_bounds__(256) void k_attn(
    const float* __restrict__ v, float* __restrict__ out)
{
    extern __shared__ float sm3[];
    float* Tq = sm3;                  // [4][TS]
    float* Tk = Tq + 4 * TS;          // [93][TS]
    float* vg = Tk + NTT * TS;        // [93][64]
    float* Gr = vg + NTT * EVD;       // [4][96]

    int bh = blockIdx.x, xb = blockIdx.y;
    int tid = threadIdx.x, lane = tid & 31, warp = tid >> 5;
    int x0 = xb * 4;

    for (int g = tid; g < 4 * OO; g += 256) {
        int r = g >> 8, o = g & 255;
        if (x0 + r < NTT) Tq[r * TS + o] = d_P[0][bh][x0 + r][o];
    }
    for (int g = tid; g < NTT * OO; g += 256) {
        int t = g >> 8, o = g & 255;
        Tk[t * TS + o] = d_P[1][bh][t][o];
    }
    for (int g = tid; g < NTT * EVD; g += 256) {
        int t = g >> 6, e = g & 63;
        float s = v[((size_t)bh * NNN + 2 * t) * EVD + e]
                + v[((size_t)bh * NNN + 2 * t + 1) * EVD + e];
        if (t == 92) s += v[((size_t)bh * NNN + 186) * EVD + e];
        vg[g] = s;
    }
    __syncthreads();

    // dots: 2 warps per row; thread u = (warp&1)*32+lane handles ty = u, u+64
    {
        int r = warp >> 1;
        int x = x0 + r;
        if (x < NTT) {
            int u = ((warp & 1) << 5) + lane;   // 0..63
            const float4* tq = (const float4*)(Tq + r * TS);
            int ty0 = u, ty1 = u + 64;
            int ty1c = (ty1 < NTT) ? ty1 : 0;
            const float4* k0 = (const float4*)(Tk + ty0 * TS);
            const float4* k1 = (const float4*)(Tk + ty1c * TS);
            float a0 = 0, a1 = 0;
            #pragma unroll 8
            for (int o4 = 0; o4 < OO / 4; o4++) {
                float4 qv = tq[o4];
                float4 b0 = k0[o4];
                a0 += qv.x * b0.x + qv.y * b0.y + qv.z * b0.z + qv.w * b0.w;
                float4 b1 = k1[o4];
                a1 += qv.x * b1.x + qv.y * b1.y + qv.z * b1.z + qv.w * b1.w;
            }
            Gr[r * 96 + ty0] = tanhf(a0);
            if (ty1 < NTT) Gr[r * 96 + ty1] = tanhf(a1);
        }
    }
    __syncthreads();

    // GEMV: warp -> (row r = warp>>1, e-half = (warp&1)*32 + lane)
    {
        int r = warp >> 1;
        int x = x0 + r;
        if (x < NTT) {
            int e = ((warp & 1) << 5) + lane;
            const float* gr = Gr + r * 96;
            float acc = 0.0f;
            #pragma unroll 4
            for (int ty = 0; ty < NTT; ty++)
                acc += gr[ty] * vg[ty * EVD + e];
            size_t base = ((size_t)bh * NNN + 2 * x) * EVD;
            out[base + e]       = acc;
            out[base + EVD + e] = acc;
            if (x == 92) out[((size_t)bh * NNN + 186) * EVD + e] = acc;
        }
    }
}

// ---------------------------------------------------------------------------
extern "C" void kernel_launch(void* const* d_in, const int* in_sizes, int n_in,
                              void* d_out, int out_size)
{
    const float* q   = (const float*)d_in[0];
    const float* k   = (const float*)d_in[1];
    const float* v   = (const float*)d_in[2];
    const float* Wq1 = (const float*)d_in[3];
    const float* bq1 = (const float*)d_in[4];
    const float* Wq2 = (const float*)d_in[5];
    const float* bq2 = (const float*)d_in[6];
    const float* Wk1 = (const float*)d_in[7];
    const float* bk1 = (const float*)d_in[8];
    const float* Wk2 = (const float*)d_in[9];
    const float* bk2 = (const float*)d_in[10];
    const float* Wlq = (const float*)d_in[11];
    const float* blq = (const float*)d_in[12];
    const float* Wlk = (const float*)d_in[13];
    const float* blk = (const float*)d_in[14];
    float* out = (float*)d_out;

    const int SM3 = (4 * TS + NTT * TS + NTT * EVD + 4 * 96) * 4;
    static int attr_done = 0;
    if (!attr_done) {
        cudaFuncSetAttribute(k_augment, cudaFuncAttributeMaxDynamicSharedMemorySize, AUG_SMEM);
        cudaFuncSetAttribute(k_proj, cudaFuncAttributeMaxDynamicSharedMemorySize, SM_TOT);
        cudaFuncSetAttribute(k_attn, cudaFuncAttributeMaxDynamicSharedMemorySize, SM3);
        attr_done = 1;
    }

    k_augment<<<dim3(8, 16), 256, AUG_SMEM>>>(q, k, Wq1, bq1, Wq2, bq2, Wk1, bk1, Wk2, bk2);
    k_proj<<<dim3(256, 2), 256, SM_TOT>>>(Wlq, blq, Wlk, blk);
    k_attn<<<dim3(4, 24), 256, SM3>>>(v, out);
}